// round 1
// baseline (speedup 1.0000x reference)
#include <cuda_runtime.h>
#include <math.h>

#define H 768
#define R 64
#define E 8
#define T_TOT 16384

// Scratch (device globals — no allocation allowed)
__device__ int   g_counts[E];
__device__ int   g_toks[E * T_TOT];
__device__ float g_pmax[T_TOT];

__global__ void zero_counts_kernel() {
    if (threadIdx.x < E) g_counts[threadIdx.x] = 0;
}

// ---------------------------------------------------------------------------
// Router: x_enc = x @ enc_w + enc_b  [64 tok per block]
//         logits = x_enc @ sw_w + sw_b ; softmax -> pmax, argmax -> bucket
// ---------------------------------------------------------------------------
__global__ __launch_bounds__(256) void router_kernel(
    const float* __restrict__ x, const float* __restrict__ enc_w,
    const float* __restrict__ enc_b, const float* __restrict__ sw_w,
    const float* __restrict__ sw_b)
{
    __shared__ float xsT[32][68];    // [k][t], padded (16B-aligned float4 rows)
    __shared__ float ws [32][68];    // [k][r]
    __shared__ float xenc[64][65];   // [t][r]

    const int tid = threadIdx.x;
    const int tq = tid >> 4;         // 0..15 -> token group (4 tokens)
    const int rq = tid & 15;         // 0..15 -> r group (4 cols)
    const int base_t = blockIdx.x * 64;

    float acc[4][4];
#pragma unroll
    for (int i = 0; i < 4; i++)
#pragma unroll
        for (int j = 0; j < 4; j++) acc[i][j] = 0.f;

    for (int k0 = 0; k0 < H; k0 += 32) {
        // load x tile [64 tok][32 k] transposed into xsT[k][t]
#pragma unroll
        for (int i = tid; i < 512; i += 256) {
            int t = i >> 3; int kk = (i & 7) << 2;
            float4 v = *(const float4*)(x + (size_t)(base_t + t) * H + k0 + kk);
            xsT[kk + 0][t] = v.x; xsT[kk + 1][t] = v.y;
            xsT[kk + 2][t] = v.z; xsT[kk + 3][t] = v.w;
        }
        // load enc_w tile [32 k][64 r]
#pragma unroll
        for (int i = tid; i < 512; i += 256) {
            int k = i >> 4; int rr = (i & 15) << 2;
            float4 v = *(const float4*)(enc_w + (size_t)(k0 + k) * R + rr);
            *(float4*)&ws[k][rr] = v;
        }
        __syncthreads();
#pragma unroll
        for (int k = 0; k < 32; k++) {
            float4 xv = *(const float4*)&xsT[k][tq * 4];
            float4 wv = *(const float4*)&ws[k][rq * 4];
            acc[0][0] += xv.x * wv.x; acc[0][1] += xv.x * wv.y; acc[0][2] += xv.x * wv.z; acc[0][3] += xv.x * wv.w;
            acc[1][0] += xv.y * wv.x; acc[1][1] += xv.y * wv.y; acc[1][2] += xv.y * wv.z; acc[1][3] += xv.y * wv.w;
            acc[2][0] += xv.z * wv.x; acc[2][1] += xv.z * wv.y; acc[2][2] += xv.z * wv.z; acc[2][3] += xv.z * wv.w;
            acc[3][0] += xv.w * wv.x; acc[3][1] += xv.w * wv.y; acc[3][2] += xv.w * wv.z; acc[3][3] += xv.w * wv.w;
        }
        __syncthreads();
    }

    // write x_enc (+bias) to smem
#pragma unroll
    for (int j = 0; j < 4; j++) {
        float b = enc_b[rq * 4 + j];
#pragma unroll
        for (int i = 0; i < 4; i++)
            xenc[tq * 4 + i][rq * 4 + j] = acc[i][j] + b;
    }
    __syncthreads();

    // per-token logits + softmax + argmax (64 working threads)
    if (tid < 64) {
        float l[E];
#pragma unroll
        for (int e = 0; e < E; e++) l[e] = sw_b[e];
        for (int r = 0; r < R; r++) {
            float xv = xenc[tid][r];
#pragma unroll
            for (int e = 0; e < E; e++) l[e] += xv * sw_w[r * E + e];
        }
        float m = l[0]; int am = 0;
#pragma unroll
        for (int e = 1; e < E; e++) { if (l[e] > m) { m = l[e]; am = e; } }
        float s = 0.f;
#pragma unroll
        for (int e = 0; e < E; e++) s += expf(l[e] - m);
        int gt = base_t + tid;
        g_pmax[gt] = 1.0f / s;                 // max prob = exp(0)/sum
        int slot = atomicAdd(&g_counts[am], 1);
        g_toks[am * T_TOT + slot] = gt;
    }
}

// ---------------------------------------------------------------------------
// Expert FFN: for expert e, tile of 64 routed tokens:
//   h = gelu(Xg @ w1[e] + b1[e])  [64,64]
//   out = (h @ w2[e] + b2[e]) * pmax   -> scatter rows
// ---------------------------------------------------------------------------
__global__ __launch_bounds__(256) void expert_kernel(
    const float* __restrict__ x, const float* __restrict__ w1,
    const float* __restrict__ b1, const float* __restrict__ w2,
    const float* __restrict__ b2, float* __restrict__ out)
{
    __shared__ float pool[4352];     // phase1: xsT[32][68] + ws[32][68]; phase2: w2t[64][68]
    __shared__ float hs[64][68];     // h transposed: [r][t]
    __shared__ int   tok_s[64];
    __shared__ float pm_s[64];

    const int e   = blockIdx.y;
    const int cnt = g_counts[e];
    const int t0  = blockIdx.x * 64;
    if (t0 >= cnt) return;
    const int nt = min(64, cnt - t0);

    const int tid = threadIdx.x;
    const int tq = tid >> 4;
    const int rq = tid & 15;

    if (tid < 64) {
        int idx = t0 + ((tid < nt) ? tid : 0);   // clamp to a valid slot
        int tok = g_toks[e * T_TOT + idx];
        tok_s[tid] = tok;
        pm_s[tid]  = g_pmax[tok];
    }
    __syncthreads();

    float (*xsT)[68] = (float(*)[68])pool;
    float (*ws)[68]  = (float(*)[68])(pool + 32 * 68);

    // ---- Phase 1: h = gelu(Xg @ w1[e] + b1[e]) ----
    float acc[4][4];
#pragma unroll
    for (int i = 0; i < 4; i++)
#pragma unroll
        for (int j = 0; j < 4; j++) acc[i][j] = 0.f;

    const float* w1e = w1 + (size_t)e * H * R;

    for (int k0 = 0; k0 < H; k0 += 32) {
#pragma unroll
        for (int i = tid; i < 512; i += 256) {
            int t = i >> 3; int kk = (i & 7) << 2;
            float4 v = *(const float4*)(x + (size_t)tok_s[t] * H + k0 + kk);
            xsT[kk + 0][t] = v.x; xsT[kk + 1][t] = v.y;
            xsT[kk + 2][t] = v.z; xsT[kk + 3][t] = v.w;
        }
#pragma unroll
        for (int i = tid; i < 512; i += 256) {
            int k = i >> 4; int rr = (i & 15) << 2;
            float4 v = *(const float4*)(w1e + (size_t)(k0 + k) * R + rr);
            *(float4*)&ws[k][rr] = v;
        }
        __syncthreads();
#pragma unroll
        for (int k = 0; k < 32; k++) {
            float4 xv = *(const float4*)&xsT[k][tq * 4];
            float4 wv = *(const float4*)&ws[k][rq * 4];
            acc[0][0] += xv.x * wv.x; acc[0][1] += xv.x * wv.y; acc[0][2] += xv.x * wv.z; acc[0][3] += xv.x * wv.w;
            acc[1][0] += xv.y * wv.x; acc[1][1] += xv.y * wv.y; acc[1][2] += xv.y * wv.z; acc[1][3] += xv.y * wv.w;
            acc[2][0] += xv.z * wv.x; acc[2][1] += xv.z * wv.y; acc[2][2] += xv.z * wv.z; acc[2][3] += xv.z * wv.w;
            acc[3][0] += xv.w * wv.x; acc[3][1] += xv.w * wv.y; acc[3][2] += xv.w * wv.z; acc[3][3] += xv.w * wv.w;
        }
        __syncthreads();
    }

    // bias + exact gelu, store transposed hs[r][t]
#pragma unroll
    for (int j = 0; j < 4; j++) {
        float b = b1[e * R + rq * 4 + j];
#pragma unroll
        for (int i = 0; i < 4; i++) {
            float v = acc[i][j] + b;
            float g = 0.5f * v * (1.0f + erff(v * 0.70710678118654752f));
            hs[rq * 4 + j][tq * 4 + i] = g;
        }
    }
    __syncthreads();

    // ---- Phase 2: out = (h @ w2[e] + b2[e]) * pmax ----
    float (*w2t)[68] = (float(*)[68])pool;   // reuse pool
    const float* w2e = w2 + (size_t)e * R * H;

    for (int n0 = 0; n0 < H; n0 += 64) {
        // load w2 tile [64 k][64 n]
#pragma unroll
        for (int i = tid; i < 1024; i += 256) {
            int k = i >> 4; int nn = (i & 15) << 2;
            float4 v = *(const float4*)(w2e + (size_t)k * H + n0 + nn);
            *(float4*)&w2t[k][nn] = v;
        }
        __syncthreads();

        float acc2[4][4];
#pragma unroll
        for (int i = 0; i < 4; i++)
#pragma unroll
            for (int j = 0; j < 4; j++) acc2[i][j] = 0.f;

#pragma unroll
        for (int k = 0; k < 64; k++) {
            float4 hv = *(const float4*)&hs[k][tq * 4];
            float4 wv = *(const float4*)&w2t[k][rq * 4];
            acc2[0][0] += hv.x * wv.x; acc2[0][1] += hv.x * wv.y; acc2[0][2] += hv.x * wv.z; acc2[0][3] += hv.x * wv.w;
            acc2[1][0] += hv.y * wv.x; acc2[1][1] += hv.y * wv.y; acc2[1][2] += hv.y * wv.z; acc2[1][3] += hv.y * wv.w;
            acc2[2][0] += hv.z * wv.x; acc2[2][1] += hv.z * wv.y; acc2[2][2] += hv.z * wv.z; acc2[2][3] += hv.z * wv.w;
            acc2[3][0] += hv.w * wv.x; acc2[3][1] += hv.w * wv.y; acc2[3][2] += hv.w * wv.z; acc2[3][3] += hv.w * wv.w;
        }

        float4 bv = *(const float4*)(b2 + (size_t)e * H + n0 + rq * 4);
#pragma unroll
        for (int i = 0; i < 4; i++) {
            int t = tq * 4 + i;
            if (t < nt) {
                float pm = pm_s[t];
                float4 o;
                o.x = (acc2[i][0] + bv.x) * pm;
                o.y = (acc2[i][1] + bv.y) * pm;
                o.z = (acc2[i][2] + bv.z) * pm;
                o.w = (acc2[i][3] + bv.w) * pm;
                *(float4*)(out + (size_t)tok_s[t] * H + n0 + rq * 4) = o;
            }
        }
        __syncthreads();
    }
}

extern "C" void kernel_launch(void* const* d_in, const int* in_sizes, int n_in,
                              void* d_out, int out_size) {
    const float* x     = (const float*)d_in[0];
    const float* enc_w = (const float*)d_in[1];
    const float* enc_b = (const float*)d_in[2];
    const float* sw_w  = (const float*)d_in[3];
    const float* sw_b  = (const float*)d_in[4];
    const float* w1    = (const float*)d_in[5];
    const float* b1    = (const float*)d_in[6];
    const float* w2    = (const float*)d_in[7];
    const float* b2    = (const float*)d_in[8];
    float* out = (float*)d_out;

    zero_counts_kernel<<<1, 32>>>();
    router_kernel<<<T_TOT / 64, 256>>>(x, enc_w, enc_b, sw_w, sw_b);
    expert_kernel<<<dim3(T_TOT / 64, E), 256>>>(x, w1, b1, w2, b2, out);
}

// round 2
// speedup vs baseline: 1.5842x; 1.5842x over previous
#include <cuda_runtime.h>
#include <math.h>

#define H 768
#define R 64
#define E 8
#define T_TOT 16384

// Scratch (device globals — no allocation allowed)
__device__ int   g_counts[E];
__device__ int   g_toks[E * T_TOT];
__device__ float g_pmax[T_TOT];

__global__ void zero_counts_kernel() {
    if (threadIdx.x < E) g_counts[threadIdx.x] = 0;
}

// acc[8][4] += xs[8] (tokens) ⊗ wv (4 cols)
__device__ __forceinline__ void fma8x4(float acc[8][4], const float* xs, float4 wv) {
#pragma unroll
    for (int i = 0; i < 8; i++) {
        acc[i][0] += xs[i] * wv.x;
        acc[i][1] += xs[i] * wv.y;
        acc[i][2] += xs[i] * wv.z;
        acc[i][3] += xs[i] * wv.w;
    }
}

// ---------------------------------------------------------------------------
// Router: x_enc = x @ enc_w + enc_b (64 tok x 64 R per block, 128 thr,
// double-buffered 32-k tiles), then switch logits + softmax + argmax bucket.
// ---------------------------------------------------------------------------
__global__ __launch_bounds__(128) void router_kernel(
    const float* __restrict__ x, const float* __restrict__ enc_w,
    const float* __restrict__ enc_b, const float* __restrict__ sw_w,
    const float* __restrict__ sw_b)
{
    __shared__ float xsT[2][32][68];   // [buf][k][t]
    __shared__ float ws [2][32][68];   // [buf][k][r]
    __shared__ float xenc[64][65];     // [t][r]

    const int tid = threadIdx.x;
    const int tq  = tid >> 4;          // 0..7  -> 8 tokens each
    const int rq  = tid & 15;          // 0..15 -> 4 R-cols each
    const int base_t = blockIdx.x * 64;

    // Per-thread load-index precompute (constant across k-tiles)
    int tA[4], kkA[4], kB[4], rrB[4];
    const float* xg[4];
#pragma unroll
    for (int j = 0; j < 4; j++) {
        int i = tid + j * 128;
        tA[j]  = i >> 3;        kkA[j] = (i & 7) << 2;
        kB[j]  = i >> 4;        rrB[j] = (i & 15) << 2;
        xg[j]  = x + (size_t)(base_t + tA[j]) * H + kkA[j];
    }

    float acc[8][4];
#pragma unroll
    for (int i = 0; i < 8; i++)
#pragma unroll
        for (int j = 0; j < 4; j++) acc[i][j] = 0.f;

    float4 xr[4], wr[4];

#define R_LOAD(k0) { \
    _Pragma("unroll") for (int j = 0; j < 4; j++) \
        xr[j] = *(const float4*)(xg[j] + (k0)); \
    _Pragma("unroll") for (int j = 0; j < 4; j++) \
        wr[j] = *(const float4*)(enc_w + (size_t)((k0) + kB[j]) * R + rrB[j]); }

#define R_STORE(b) { \
    _Pragma("unroll") for (int j = 0; j < 4; j++) { \
        xsT[b][kkA[j] + 0][tA[j]] = xr[j].x; xsT[b][kkA[j] + 1][tA[j]] = xr[j].y; \
        xsT[b][kkA[j] + 2][tA[j]] = xr[j].z; xsT[b][kkA[j] + 3][tA[j]] = xr[j].w; } \
    _Pragma("unroll") for (int j = 0; j < 4; j++) \
        *(float4*)&ws[b][kB[j]][rrB[j]] = wr[j]; }

    R_LOAD(0); R_STORE(0); __syncthreads();
    int p = 0;
    for (int it = 0; it < 24; it++) {
        if (it < 23) R_LOAD((it + 1) * 32);
#pragma unroll 8
        for (int k = 0; k < 32; k++) {
            float4 wv = *(const float4*)&ws[p][k][rq * 4];
            float4 xa = *(const float4*)&xsT[p][k][tq * 8];
            float4 xb = *(const float4*)&xsT[p][k][tq * 8 + 4];
            float xs[8] = {xa.x, xa.y, xa.z, xa.w, xb.x, xb.y, xb.z, xb.w};
            fma8x4(acc, xs, wv);
        }
        if (it < 23) R_STORE(p ^ 1);
        __syncthreads();
        p ^= 1;
    }

    // x_enc (+bias) -> smem
    {
        float4 bv = *(const float4*)(enc_b + rq * 4);
        float bb[4] = {bv.x, bv.y, bv.z, bv.w};
#pragma unroll
        for (int i = 0; i < 8; i++)
#pragma unroll
            for (int j = 0; j < 4; j++)
                xenc[tq * 8 + i][rq * 4 + j] = acc[i][j] + bb[j];
    }
    __syncthreads();

    // switch logits: 2 threads per token, shfl reduce
    {
        int t = tid >> 1, hf = tid & 1;
        float l[E];
#pragma unroll
        for (int e = 0; e < E; e++) l[e] = hf ? 0.f : sw_b[e];
        int r0 = hf * 32;
        for (int r = r0; r < r0 + 32; r++) {
            float xv = xenc[t][r];
#pragma unroll
            for (int e = 0; e < E; e++) l[e] += xv * sw_w[r * E + e];
        }
#pragma unroll
        for (int e = 0; e < E; e++) l[e] += __shfl_xor_sync(0xffffffffu, l[e], 1);
        if (hf == 0) {
            float m = l[0]; int am = 0;
#pragma unroll
            for (int e = 1; e < E; e++) { if (l[e] > m) { m = l[e]; am = e; } }
            float s = 0.f;
#pragma unroll
            for (int e = 0; e < E; e++) s += expf(l[e] - m);
            int gt = base_t + t;
            g_pmax[gt] = 1.0f / s;
            int slot = atomicAdd(&g_counts[am], 1);
            g_toks[am * T_TOT + slot] = gt;
        }
    }
}

// ---------------------------------------------------------------------------
// Expert FFN: 64 routed tokens per block, 128 threads.
//   Phase 1: h = gelu(Xg @ w1[e] + b1[e])  [64,64]  (double-buffered k)
//   Phase 2: out = (h @ w2[e] + b2[e]) * pmax       (double-buffered w2 tiles)
// ---------------------------------------------------------------------------
__global__ __launch_bounds__(128) void expert_kernel(
    const float* __restrict__ x, const float* __restrict__ w1,
    const float* __restrict__ b1, const float* __restrict__ w2,
    const float* __restrict__ b2, float* __restrict__ outp)
{
    __shared__ float pool[8704];     // phase1: xsT[2][32][68] + ws[2][32][68]; phase2: w2t[2][64][68]
    __shared__ float hs[64][68];     // h transposed: [r][t]
    __shared__ int   tok_s[64];
    __shared__ float pm_s[64];

    const int e   = blockIdx.y;
    const int cnt = g_counts[e];
    const int t0  = blockIdx.x * 64;
    if (t0 >= cnt) return;
    const int nt = min(64, cnt - t0);

    const int tid = threadIdx.x;
    const int tq  = tid >> 4;
    const int rq  = tid & 15;

    if (tid < 64) {
        int idx = t0 + ((tid < nt) ? tid : 0);    // clamp to a valid slot
        int tok = g_toks[e * T_TOT + idx];
        tok_s[tid] = tok;
        pm_s[tid]  = g_pmax[tok];
    }
    __syncthreads();

    float (*xsT)[32][68] = (float(*)[32][68])pool;            // [2][32][68]
    float (*wsp)[32][68] = (float(*)[32][68])(pool + 4352);   // [2][32][68]

    int tA[4], kkA[4], kB[4], rrB[4];
    const float* xg[4];
#pragma unroll
    for (int j = 0; j < 4; j++) {
        int i = tid + j * 128;
        tA[j]  = i >> 3;        kkA[j] = (i & 7) << 2;
        kB[j]  = i >> 4;        rrB[j] = (i & 15) << 2;
        xg[j]  = x + (size_t)tok_s[tA[j]] * H + kkA[j];
    }

    const float* w1e = w1 + (size_t)e * H * R;

    float acc[8][4];
#pragma unroll
    for (int i = 0; i < 8; i++)
#pragma unroll
        for (int j = 0; j < 4; j++) acc[i][j] = 0.f;

    float4 xr[4], wr[4];

#define E_LOAD(k0) { \
    _Pragma("unroll") for (int j = 0; j < 4; j++) \
        xr[j] = *(const float4*)(xg[j] + (k0)); \
    _Pragma("unroll") for (int j = 0; j < 4; j++) \
        wr[j] = *(const float4*)(w1e + (size_t)((k0) + kB[j]) * R + rrB[j]); }

#define E_STORE(b) { \
    _Pragma("unroll") for (int j = 0; j < 4; j++) { \
        xsT[b][kkA[j] + 0][tA[j]] = xr[j].x; xsT[b][kkA[j] + 1][tA[j]] = xr[j].y; \
        xsT[b][kkA[j] + 2][tA[j]] = xr[j].z; xsT[b][kkA[j] + 3][tA[j]] = xr[j].w; } \
    _Pragma("unroll") for (int j = 0; j < 4; j++) \
        *(float4*)&wsp[b][kB[j]][rrB[j]] = wr[j]; }

    E_LOAD(0); E_STORE(0); __syncthreads();
    int p = 0;
    for (int it = 0; it < 24; it++) {
        if (it < 23) E_LOAD((it + 1) * 32);
#pragma unroll 8
        for (int k = 0; k < 32; k++) {
            float4 wv = *(const float4*)&wsp[p][k][rq * 4];
            float4 xa = *(const float4*)&xsT[p][k][tq * 8];
            float4 xb = *(const float4*)&xsT[p][k][tq * 8 + 4];
            float xs[8] = {xa.x, xa.y, xa.z, xa.w, xb.x, xb.y, xb.z, xb.w};
            fma8x4(acc, xs, wv);
        }
        if (it < 23) E_STORE(p ^ 1);
        __syncthreads();
        p ^= 1;
    }

    // bias + exact gelu, store transposed hs[r][t]
    {
        float4 bv = *(const float4*)(b1 + (size_t)e * R + rq * 4);
        float bb[4] = {bv.x, bv.y, bv.z, bv.w};
#pragma unroll
        for (int j = 0; j < 4; j++)
#pragma unroll
            for (int i = 0; i < 8; i++) {
                float v = acc[i][j] + bb[j];
                float g = 0.5f * v * (1.0f + erff(v * 0.70710678118654752f));
                hs[rq * 4 + j][tq * 8 + i] = g;
            }
    }
    __syncthreads();

    // ---- Phase 2 ----
    float (*w2t)[64][68] = (float(*)[64][68])pool;   // [2][64][68] overlays phase-1 buffers
    const float* w2e = w2 + (size_t)e * R * H;

    int kC[8], nnC[8];
#pragma unroll
    for (int j = 0; j < 8; j++) {
        int i = tid + j * 128;
        kC[j] = i >> 4;  nnC[j] = (i & 15) << 2;
    }
    float4 w2r[8];

#define W2_LOAD(n0) { \
    _Pragma("unroll") for (int j = 0; j < 8; j++) \
        w2r[j] = *(const float4*)(w2e + (size_t)kC[j] * H + (n0) + nnC[j]); }
#define W2_STORE(b) { \
    _Pragma("unroll") for (int j = 0; j < 8; j++) \
        *(float4*)&w2t[b][kC[j]][nnC[j]] = w2r[j]; }

    W2_LOAD(0); W2_STORE(0); __syncthreads();
    int p2 = 0;
    for (int ni = 0; ni < 12; ni++) {
        int n0 = ni * 64;
        if (ni < 11) W2_LOAD(n0 + 64);

        float acc2[8][4];
#pragma unroll
        for (int i = 0; i < 8; i++)
#pragma unroll
            for (int j = 0; j < 4; j++) acc2[i][j] = 0.f;

#pragma unroll 8
        for (int k = 0; k < 64; k++) {
            float4 wv = *(const float4*)&w2t[p2][k][rq * 4];
            float4 ha = *(const float4*)&hs[k][tq * 8];
            float4 hb = *(const float4*)&hs[k][tq * 8 + 4];
            float xs[8] = {ha.x, ha.y, ha.z, ha.w, hb.x, hb.y, hb.z, hb.w};
            fma8x4(acc2, xs, wv);
        }

        float4 bv = *(const float4*)(b2 + (size_t)e * H + n0 + rq * 4);
#pragma unroll
        for (int i = 0; i < 8; i++) {
            int t = tq * 8 + i;
            if (t < nt) {
                float pm = pm_s[t];
                float4 o;
                o.x = (acc2[i][0] + bv.x) * pm;
                o.y = (acc2[i][1] + bv.y) * pm;
                o.z = (acc2[i][2] + bv.z) * pm;
                o.w = (acc2[i][3] + bv.w) * pm;
                *(float4*)(outp + (size_t)tok_s[t] * H + n0 + rq * 4) = o;
            }
        }
        if (ni < 11) W2_STORE(p2 ^ 1);
        __syncthreads();
        p2 ^= 1;
    }
}

extern "C" void kernel_launch(void* const* d_in, const int* in_sizes, int n_in,
                              void* d_out, int out_size) {
    const float* x     = (const float*)d_in[0];
    const float* enc_w = (const float*)d_in[1];
    const float* enc_b = (const float*)d_in[2];
    const float* sw_w  = (const float*)d_in[3];
    const float* sw_b  = (const float*)d_in[4];
    const float* w1    = (const float*)d_in[5];
    const float* b1    = (const float*)d_in[6];
    const float* w2    = (const float*)d_in[7];
    const float* b2    = (const float*)d_in[8];
    float* out = (float*)d_out;

    zero_counts_kernel<<<1, 32>>>();
    router_kernel<<<T_TOT / 64, 128>>>(x, enc_w, enc_b, sw_w, sw_b);
    expert_kernel<<<dim3(T_TOT / 64, E), 128>>>(x, w1, b1, w2, b2, out);
}

// round 4
// speedup vs baseline: 3.1625x; 1.9963x over previous
#include <cuda_runtime.h>
#include <math.h>
#include <stdint.h>

#define H 768
#define R 64
#define E 8
#define T_TOT 16384
#define T_TILE 128

// ---------------- device global scratch -----------------------------------
__device__ int   g_counts[E];
__device__ int   g_toks[E * T_TOT];
__device__ float g_pmax[T_TOT];

__global__ void zero_counts_kernel() {
    if (threadIdx.x < E) g_counts[threadIdx.x] = 0;
}

// ---------------- helpers ---------------------------------------------------
__device__ __forceinline__ float tf32f(float v) {
    uint32_t r; asm("cvt.rna.tf32.f32 %0, %1;" : "=r"(r) : "f"(v));
    return __uint_as_float(r);
}
__device__ __forceinline__ float gelu(float v) {
    return 0.5f * v * (1.0f + erff(v * 0.70710678118654752f));
}
__device__ __forceinline__ void mma_tf32(float c[4], uint32_t a0, uint32_t a1,
                                         uint32_t a2, uint32_t a3,
                                         uint32_t b0, uint32_t b1) {
    asm volatile(
        "mma.sync.aligned.m16n8k8.row.col.f32.tf32.tf32.f32 "
        "{%0,%1,%2,%3}, {%4,%5,%6,%7}, {%8,%9}, {%0,%1,%2,%3};"
        : "+f"(c[0]), "+f"(c[1]), "+f"(c[2]), "+f"(c[3])
        : "r"(a0), "r"(a1), "r"(a2), "r"(a3), "r"(b0), "r"(b1));
}
#define FB(x) __float_as_uint(x)

// ---------------- router (fp32 SIMT, proven round-2) ------------------------
__device__ __forceinline__ void fma8x4(float acc[8][4], const float* xs, float4 wv) {
#pragma unroll
    for (int i = 0; i < 8; i++) {
        acc[i][0] += xs[i] * wv.x; acc[i][1] += xs[i] * wv.y;
        acc[i][2] += xs[i] * wv.z; acc[i][3] += xs[i] * wv.w;
    }
}

__global__ __launch_bounds__(128) void router_kernel(
    const float* __restrict__ x, const float* __restrict__ enc_w,
    const float* __restrict__ enc_b, const float* __restrict__ sw_w,
    const float* __restrict__ sw_b)
{
    __shared__ float xsT[2][32][68];
    __shared__ float ws [2][32][68];
    __shared__ float xenc[64][65];

    const int tid = threadIdx.x;
    const int tq  = tid >> 4;
    const int rq  = tid & 15;
    const int base_t = blockIdx.x * 64;

    int tA[4], kkA[4], kB[4], rrB[4];
    const float* xg[4];
#pragma unroll
    for (int j = 0; j < 4; j++) {
        int i = tid + j * 128;
        tA[j] = i >> 3;  kkA[j] = (i & 7) << 2;
        kB[j] = i >> 4;  rrB[j] = (i & 15) << 2;
        xg[j] = x + (size_t)(base_t + tA[j]) * H + kkA[j];
    }

    float acc[8][4];
#pragma unroll
    for (int i = 0; i < 8; i++)
#pragma unroll
        for (int j = 0; j < 4; j++) acc[i][j] = 0.f;

    float4 xr[4], wr[4];
#define R_LOAD(k0) { \
    _Pragma("unroll") for (int j = 0; j < 4; j++) xr[j] = *(const float4*)(xg[j] + (k0)); \
    _Pragma("unroll") for (int j = 0; j < 4; j++) wr[j] = *(const float4*)(enc_w + (size_t)((k0) + kB[j]) * R + rrB[j]); }
#define R_STORE(b) { \
    _Pragma("unroll") for (int j = 0; j < 4; j++) { \
        xsT[b][kkA[j]+0][tA[j]] = xr[j].x; xsT[b][kkA[j]+1][tA[j]] = xr[j].y; \
        xsT[b][kkA[j]+2][tA[j]] = xr[j].z; xsT[b][kkA[j]+3][tA[j]] = xr[j].w; } \
    _Pragma("unroll") for (int j = 0; j < 4; j++) *(float4*)&ws[b][kB[j]][rrB[j]] = wr[j]; }

    R_LOAD(0); R_STORE(0); __syncthreads();
    int p = 0;
    for (int it = 0; it < 24; it++) {
        if (it < 23) R_LOAD((it + 1) * 32);
#pragma unroll 8
        for (int k = 0; k < 32; k++) {
            float4 wv = *(const float4*)&ws[p][k][rq * 4];
            float4 xa = *(const float4*)&xsT[p][k][tq * 8];
            float4 xb = *(const float4*)&xsT[p][k][tq * 8 + 4];
            float xs[8] = {xa.x, xa.y, xa.z, xa.w, xb.x, xb.y, xb.z, xb.w};
            fma8x4(acc, xs, wv);
        }
        if (it < 23) R_STORE(p ^ 1);
        __syncthreads();
        p ^= 1;
    }
    {
        float4 bv = *(const float4*)(enc_b + rq * 4);
        float bb[4] = {bv.x, bv.y, bv.z, bv.w};
#pragma unroll
        for (int i = 0; i < 8; i++)
#pragma unroll
            for (int j = 0; j < 4; j++)
                xenc[tq * 8 + i][rq * 4 + j] = acc[i][j] + bb[j];
    }
    __syncthreads();
    {
        int t = tid >> 1, hf = tid & 1;
        float l[E];
#pragma unroll
        for (int e = 0; e < E; e++) l[e] = hf ? 0.f : sw_b[e];
        int r0 = hf * 32;
        for (int r = r0; r < r0 + 32; r++) {
            float xv = xenc[t][r];
#pragma unroll
            for (int e = 0; e < E; e++) l[e] += xv * sw_w[r * E + e];
        }
#pragma unroll
        for (int e = 0; e < E; e++) l[e] += __shfl_xor_sync(0xffffffffu, l[e], 1);
        if (hf == 0) {
            float m = l[0]; int am = 0;
#pragma unroll
            for (int e = 1; e < E; e++) { if (l[e] > m) { m = l[e]; am = e; } }
            float s = 0.f;
#pragma unroll
            for (int e = 0; e < E; e++) s += expf(l[e] - m);
            int gt = base_t + t;
            g_pmax[gt] = 1.0f / s;
            int slot = atomicAdd(&g_counts[am], 1);
            g_toks[am * T_TOT + slot] = gt;
        }
    }
}

// ---------------- expert kernel: mma.sync tf32 ------------------------------
// smem layout (bytes; padded strides chosen for conflict-free fragment LDS):
//   HS  [128][68]  f32 @ 0          (34816)  h-activations (phase2 A)
//   POOL @ 34816:
//     phase1: XS[2][128][36] (36864) + WS[2][32][72] (18432)
//     phase2: W2S[2][64][136] (69632)
//   TOK[128] @ 104448, PM[128] @ 104960, B1S[64] @ 105472, B2S[2][128] @ 105728
#define OFF_HS    0
#define OFF_POOL  34816
#define OFF_WS    (34816 + 36864)
#define OFF_TOK   104448
#define OFF_PM    104960
#define OFF_B1S   105472
#define OFF_B2S   105728
#define SMEM_TOTAL (105728 + 1024)

#define XS_STR  36
#define WS_STR  72
#define HS_STR  68
#define W2_STR  136

__global__ void __launch_bounds__(256)
expert_mma_kernel(const float* __restrict__ x,  const float* __restrict__ w1,
                  const float* __restrict__ b1, const float* __restrict__ w2,
                  const float* __restrict__ b2, float* __restrict__ outp)
{
    extern __shared__ char smem[];
    const int e   = blockIdx.y;
    const int cnt = g_counts[e];
    const int t0  = blockIdx.x * T_TILE;
    if (t0 >= cnt) return;
    const int nt = min(T_TILE, cnt - t0);

    const int tid  = threadIdx.x;
    const int wid  = tid >> 5;
    const int lane = tid & 31;
    const int lr   = lane >> 2;      // 0..7
    const int lc   = lane & 3;       // 0..3
    const int m0   = wid * 16;       // warp's token-row base

    float* HS  = (float*)(smem + OFF_HS);
    float* XS  = (float*)(smem + OFF_POOL);
    float* WS  = (float*)(smem + OFF_WS);
    float* W2S = (float*)(smem + OFF_POOL);
    int*   toks = (int*)(smem + OFF_TOK);
    float* pm_s = (float*)(smem + OFF_PM);
    float* b1s  = (float*)(smem + OFF_B1S);
    float* b2s  = (float*)(smem + OFF_B2S);

    if (tid < 128) {
        int idx = t0 + ((tid < nt) ? tid : 0);
        int tok = g_toks[e * T_TOT + idx];
        toks[tid] = tok;
        pm_s[tid] = g_pmax[tok];
    }
    if (tid < 64) b1s[tid] = b1[e * R + tid];
    __syncthreads();

    // ======== Phase 1: C1[128,64] = X[128,768] @ W1[768,64] ========
    const float* w1e = w1 + (size_t)e * H * R;
    int xrow[4], xk[4];
    const float* xgp[4];
#pragma unroll
    for (int j = 0; j < 4; j++) {
        int i = tid + j * 256;
        xrow[j] = i >> 3;  xk[j] = (i & 7) << 2;
        xgp[j] = x + (size_t)toks[xrow[j]] * H + xk[j];
    }
    int wkr[2], wn4[2];
#pragma unroll
    for (int j = 0; j < 2; j++) {
        int i = tid + j * 256;
        wkr[j] = i >> 4;  wn4[j] = (i & 15) << 2;
    }

    float4 xr[4], wr[2];
#define P1_LOAD(k0) { \
    _Pragma("unroll") for (int j = 0; j < 4; j++) xr[j] = *(const float4*)(xgp[j] + (k0)); \
    _Pragma("unroll") for (int j = 0; j < 2; j++) wr[j] = *(const float4*)(w1e + (size_t)((k0) + wkr[j]) * R + wn4[j]); }
#define P1_STORE(bf) { \
    _Pragma("unroll") for (int j = 0; j < 4; j++) { \
        float* d = XS + ((size_t)((bf) * 128 + xrow[j]) * XS_STR + xk[j]); \
        d[0] = tf32f(xr[j].x); d[1] = tf32f(xr[j].y); d[2] = tf32f(xr[j].z); d[3] = tf32f(xr[j].w); } \
    _Pragma("unroll") for (int j = 0; j < 2; j++) { \
        float* d = WS + ((size_t)((bf) * 32 + wkr[j]) * WS_STR + wn4[j]); \
        d[0] = tf32f(wr[j].x); d[1] = tf32f(wr[j].y); d[2] = tf32f(wr[j].z); d[3] = tf32f(wr[j].w); } }

    float acc[8][4];
#pragma unroll
    for (int i = 0; i < 8; i++)
#pragma unroll
        for (int j = 0; j < 4; j++) acc[i][j] = 0.f;

    P1_LOAD(0); P1_STORE(0); __syncthreads();
    int p = 0;
    for (int it = 0; it < 24; it++) {
        if (it < 23) P1_LOAD((it + 1) * 32);
#pragma unroll
        for (int ks = 0; ks < 4; ks++) {
            const int kk = ks * 8;
            const float* xb = XS + (size_t)(p * 128 + m0) * XS_STR + kk;
            uint32_t a0 = FB(xb[(size_t)lr * XS_STR + lc]);
            uint32_t a1 = FB(xb[(size_t)(lr + 8) * XS_STR + lc]);
            uint32_t a2 = FB(xb[(size_t)lr * XS_STR + lc + 4]);
            uint32_t a3 = FB(xb[(size_t)(lr + 8) * XS_STR + lc + 4]);
            const float* wb0 = WS + (size_t)(p * 32 + kk + lc) * WS_STR + lr;
            const float* wb1 = WS + (size_t)(p * 32 + kk + lc + 4) * WS_STR + lr;
#pragma unroll
            for (int ntile = 0; ntile < 8; ntile++) {
                uint32_t b0 = FB(wb0[ntile * 8]);
                uint32_t b1v = FB(wb1[ntile * 8]);
                mma_tf32(acc[ntile], a0, a1, a2, a3, b0, b1v);
            }
        }
        if (it < 23) P1_STORE(p ^ 1);
        __syncthreads();
        p ^= 1;
    }

    // bias + gelu -> HS (tf32-rounded, phase2 A operand)
#pragma unroll
    for (int ntile = 0; ntile < 8; ntile++) {
        const int cb = ntile * 8 + 2 * lc;
        const float bva = b1s[cb], bvb = b1s[cb + 1];
        float* h0 = HS + (size_t)(m0 + lr) * HS_STR + cb;
        float* h1 = HS + (size_t)(m0 + lr + 8) * HS_STR + cb;
        h0[0] = tf32f(gelu(acc[ntile][0] + bva));
        h0[1] = tf32f(gelu(acc[ntile][1] + bvb));
        h1[0] = tf32f(gelu(acc[ntile][2] + bva));
        h1[1] = tf32f(gelu(acc[ntile][3] + bvb));
    }
    __syncthreads();

    // ======== Phase 2: out[128,768] = gelu_h[128,64] @ W2[64,768] ========
    const float* w2e = w2 + (size_t)e * R * H;
    int w2k[8], w2n[8];
#pragma unroll
    for (int j = 0; j < 8; j++) {
        int i = tid + j * 256;
        w2k[j] = i >> 5;  w2n[j] = (i & 31) << 2;
    }
    float4 w2r[8];
#define P2_LOAD(n0) { \
    _Pragma("unroll") for (int j = 0; j < 8; j++) \
        w2r[j] = *(const float4*)(w2e + (size_t)w2k[j] * H + (n0) + w2n[j]); }
#define P2_STORE(bf) { \
    _Pragma("unroll") for (int j = 0; j < 8; j++) { \
        float* d = W2S + ((size_t)((bf) * 64 + w2k[j]) * W2_STR + w2n[j]); \
        d[0] = tf32f(w2r[j].x); d[1] = tf32f(w2r[j].y); d[2] = tf32f(w2r[j].z); d[3] = tf32f(w2r[j].w); } }

    P2_LOAD(0); P2_STORE(0);
    if (tid < 128) b2s[tid] = b2[(size_t)e * H + tid];
    __syncthreads();

    const bool ok0 = (m0 + lr) < nt;
    const bool ok1 = (m0 + lr + 8) < nt;
    const float pm0 = pm_s[m0 + lr];
    const float pm1 = pm_s[m0 + lr + 8];
    float* orow0 = outp + (size_t)toks[m0 + lr] * H;
    float* orow1 = outp + (size_t)toks[m0 + lr + 8] * H;

    // preload phase2 A fragments once (K=64 fixed)
    uint32_t af[8][4];
#pragma unroll
    for (int ks = 0; ks < 8; ks++) {
        const int kk = ks * 8;
        const float* hb = HS + (size_t)m0 * HS_STR + kk;
        af[ks][0] = FB(hb[(size_t)lr * HS_STR + lc]);
        af[ks][1] = FB(hb[(size_t)(lr + 8) * HS_STR + lc]);
        af[ks][2] = FB(hb[(size_t)lr * HS_STR + lc + 4]);
        af[ks][3] = FB(hb[(size_t)(lr + 8) * HS_STR + lc + 4]);
    }

    int bf = 0;
    for (int nc = 0; nc < 6; nc++) {
        const int n0 = nc * 128;
        if (nc < 5) P2_LOAD(n0 + 128);

        float acc2[16][4];
#pragma unroll
        for (int i = 0; i < 16; i++)
#pragma unroll
            for (int j = 0; j < 4; j++) acc2[i][j] = 0.f;

#pragma unroll
        for (int ks = 0; ks < 8; ks++) {
            const int kk = ks * 8;
            const float* wb0 = W2S + (size_t)(bf * 64 + kk + lc) * W2_STR + lr;
            const float* wb1 = W2S + (size_t)(bf * 64 + kk + lc + 4) * W2_STR + lr;
#pragma unroll
            for (int ntile = 0; ntile < 16; ntile++) {
                uint32_t b0 = FB(wb0[ntile * 8]);
                uint32_t b1v = FB(wb1[ntile * 8]);
                mma_tf32(acc2[ntile], af[ks][0], af[ks][1], af[ks][2], af[ks][3], b0, b1v);
            }
        }

        // epilogue: bias + pmax scale, float2 stores, row guards
#pragma unroll
        for (int ntile = 0; ntile < 16; ntile++) {
            const int cb = ntile * 8 + 2 * lc;
            const float bva = b2s[bf * 128 + cb], bvb = b2s[bf * 128 + cb + 1];
            if (ok0) {
                float2 o = { (acc2[ntile][0] + bva) * pm0, (acc2[ntile][1] + bvb) * pm0 };
                *(float2*)(orow0 + n0 + cb) = o;
            }
            if (ok1) {
                float2 o = { (acc2[ntile][2] + bva) * pm1, (acc2[ntile][3] + bvb) * pm1 };
                *(float2*)(orow1 + n0 + cb) = o;
            }
        }

        if (nc < 5) {
            P2_STORE(bf ^ 1);
            if (tid < 128) b2s[(bf ^ 1) * 128 + tid] = b2[(size_t)e * H + n0 + 128 + tid];
        }
        __syncthreads();
        bf ^= 1;
    }
}

// ---------------- launch ----------------------------------------------------
extern "C" void kernel_launch(void* const* d_in, const int* in_sizes, int n_in,
                              void* d_out, int out_size) {
    const float* x     = (const float*)d_in[0];
    const float* enc_w = (const float*)d_in[1];
    const float* enc_b = (const float*)d_in[2];
    const float* sw_w  = (const float*)d_in[3];
    const float* sw_b  = (const float*)d_in[4];
    const float* w1    = (const float*)d_in[5];
    const float* b1    = (const float*)d_in[6];
    const float* w2    = (const float*)d_in[7];
    const float* b2    = (const float*)d_in[8];
    float* out = (float*)d_out;

    cudaFuncSetAttribute(expert_mma_kernel,
                         cudaFuncAttributeMaxDynamicSharedMemorySize, SMEM_TOTAL);

    zero_counts_kernel<<<1, 32>>>();
    router_kernel<<<T_TOT / 64, 128>>>(x, enc_w, enc_b, sw_w, sw_b);
    expert_mma_kernel<<<dim3(T_TOT / T_TILE, E), 256, SMEM_TOTAL>>>(
        x, w1, b1, w2, b2, out);
}

// round 6
// speedup vs baseline: 3.2836x; 1.0383x over previous
#include <cuda_runtime.h>
#include <math.h>
#include <stdint.h>

#define H 768
#define R 64
#define E 8
#define T_TOT 16384
#define T_TILE 128

// ---------------- device global scratch -----------------------------------
__device__ int   g_counts[E];
__device__ int   g_toks[E * T_TOT];
__device__ float g_pmax[T_TOT];

__global__ void zero_counts_kernel() {
    if (threadIdx.x < E) g_counts[threadIdx.x] = 0;
}

// ---------------- helpers ---------------------------------------------------
__device__ __forceinline__ float tf32f(float v) {
    uint32_t r; asm("cvt.rna.tf32.f32 %0, %1;" : "=r"(r) : "f"(v));
    return __uint_as_float(r);
}
__device__ __forceinline__ float gelu(float v) {
    return 0.5f * v * (1.0f + erff(v * 0.70710678118654752f));
}
__device__ __forceinline__ void mma_tf32(float c[4], uint32_t a0, uint32_t a1,
                                         uint32_t a2, uint32_t a3,
                                         uint32_t b0, uint32_t b1) {
    asm volatile(
        "mma.sync.aligned.m16n8k8.row.col.f32.tf32.tf32.f32 "
        "{%0,%1,%2,%3}, {%4,%5,%6,%7}, {%8,%9}, {%0,%1,%2,%3};"
        : "+f"(c[0]), "+f"(c[1]), "+f"(c[2]), "+f"(c[3])
        : "r"(a0), "r"(a1), "r"(a2), "r"(a3), "r"(b0), "r"(b1));
}
#define FB(x) __float_as_uint(x)

// ---------------- router: 3xTF32 mma encoder + switch tail ------------------
// smem (bytes):
//   XSH[2][128][36] @ 0        (36864)   x hi   (xenc[128][68] overlays @0 later)
//   XSL[2][128][36] @ 36864    (36864)   x lo
//   WSH[2][32][72]  @ 73728    (18432)   enc_w hi
//   WSL[2][32][72]  @ 92160    (18432)   enc_w lo
//   BENC[64]        @ 110592, SWW[512] @ 110848, SWB[8] @ 112896
#define RT_XSH   0
#define RT_XSL   36864
#define RT_WSH   73728
#define RT_WSL   92160
#define RT_BENC  110592
#define RT_SWW   110848
#define RT_SWB   112896
#define SMEM_RT  113152

#define RXS_STR 36
#define RWS_STR 72
#define XE_STR  68

__global__ void __launch_bounds__(256)
router_mma_kernel(const float* __restrict__ x, const float* __restrict__ enc_w,
                  const float* __restrict__ enc_b, const float* __restrict__ sw_w,
                  const float* __restrict__ sw_b)
{
    extern __shared__ char smem[];
    const int tid  = threadIdx.x;
    const int wid  = tid >> 5;
    const int lane = tid & 31;
    const int lr   = lane >> 2;
    const int lc   = lane & 3;
    const int m0   = wid * 16;
    const int base_t = blockIdx.x * T_TILE;

    float* XSH = (float*)(smem + RT_XSH);
    float* XSL = (float*)(smem + RT_XSL);
    float* WSH = (float*)(smem + RT_WSH);
    float* WSL = (float*)(smem + RT_WSL);
    float* benc = (float*)(smem + RT_BENC);
    float* sws  = (float*)(smem + RT_SWW);
    float* swbs = (float*)(smem + RT_SWB);

    if (tid < 64)  benc[tid] = enc_b[tid];
    if (tid >= 64 && tid < 192) {
        float4 v = *(const float4*)(sw_w + (tid - 64) * 4);
        *(float4*)&sws[(tid - 64) * 4] = v;
    }
    if (tid >= 192 && tid < 200) swbs[tid - 192] = sw_b[tid - 192];

    // load-index precompute (same pattern as expert phase 1)
    int xrow[4], xk[4];
    const float* xgp[4];
#pragma unroll
    for (int j = 0; j < 4; j++) {
        int i = tid + j * 256;
        xrow[j] = i >> 3;  xk[j] = (i & 7) << 2;
        xgp[j] = x + (size_t)(base_t + xrow[j]) * H + xk[j];
    }
    int wkr[2], wn4[2];
#pragma unroll
    for (int j = 0; j < 2; j++) {
        int i = tid + j * 256;
        wkr[j] = i >> 4;  wn4[j] = (i & 15) << 2;
    }

    float4 xr[4], wr[2];
#define RT_LOAD(k0) { \
    _Pragma("unroll") for (int j = 0; j < 4; j++) xr[j] = *(const float4*)(xgp[j] + (k0)); \
    _Pragma("unroll") for (int j = 0; j < 2; j++) wr[j] = *(const float4*)(enc_w + (size_t)((k0) + wkr[j]) * R + wn4[j]); }
#define SPLIT4(hi, lo, v) { \
    hi[0] = tf32f(v.x); lo[0] = tf32f(v.x - hi[0]); \
    hi[1] = tf32f(v.y); lo[1] = tf32f(v.y - hi[1]); \
    hi[2] = tf32f(v.z); lo[2] = tf32f(v.z - hi[2]); \
    hi[3] = tf32f(v.w); lo[3] = tf32f(v.w - hi[3]); }
#define RT_STORE(bf) { \
    _Pragma("unroll") for (int j = 0; j < 4; j++) { \
        size_t o = (size_t)((bf) * 128 + xrow[j]) * RXS_STR + xk[j]; \
        float h[4], l[4]; SPLIT4(h, l, xr[j]); \
        XSH[o] = h[0]; XSH[o+1] = h[1]; XSH[o+2] = h[2]; XSH[o+3] = h[3]; \
        XSL[o] = l[0]; XSL[o+1] = l[1]; XSL[o+2] = l[2]; XSL[o+3] = l[3]; } \
    _Pragma("unroll") for (int j = 0; j < 2; j++) { \
        size_t o = (size_t)((bf) * 32 + wkr[j]) * RWS_STR + wn4[j]; \
        float h[4], l[4]; SPLIT4(h, l, wr[j]); \
        WSH[o] = h[0]; WSH[o+1] = h[1]; WSH[o+2] = h[2]; WSH[o+3] = h[3]; \
        WSL[o] = l[0]; WSL[o+1] = l[1]; WSL[o+2] = l[2]; WSL[o+3] = l[3]; } }

    float acc[8][4];
#pragma unroll
    for (int i = 0; i < 8; i++)
#pragma unroll
        for (int j = 0; j < 4; j++) acc[i][j] = 0.f;

    RT_LOAD(0); RT_STORE(0); __syncthreads();
    int p = 0;
    for (int it = 0; it < 24; it++) {
        if (it < 23) RT_LOAD((it + 1) * 32);
#pragma unroll
        for (int ks = 0; ks < 4; ks++) {
            const int kk = ks * 8;
            const float* xbh = XSH + (size_t)(p * 128 + m0) * RXS_STR + kk;
            const float* xbl = XSL + (size_t)(p * 128 + m0) * RXS_STR + kk;
            uint32_t ah0 = FB(xbh[(size_t)lr * RXS_STR + lc]);
            uint32_t ah1 = FB(xbh[(size_t)(lr + 8) * RXS_STR + lc]);
            uint32_t ah2 = FB(xbh[(size_t)lr * RXS_STR + lc + 4]);
            uint32_t ah3 = FB(xbh[(size_t)(lr + 8) * RXS_STR + lc + 4]);
            uint32_t al0 = FB(xbl[(size_t)lr * RXS_STR + lc]);
            uint32_t al1 = FB(xbl[(size_t)(lr + 8) * RXS_STR + lc]);
            uint32_t al2 = FB(xbl[(size_t)lr * RXS_STR + lc + 4]);
            uint32_t al3 = FB(xbl[(size_t)(lr + 8) * RXS_STR + lc + 4]);
            const size_t ob0 = (size_t)(p * 32 + kk + lc) * RWS_STR + lr;
            const size_t ob1 = (size_t)(p * 32 + kk + lc + 4) * RWS_STR + lr;
#pragma unroll
            for (int ntile = 0; ntile < 8; ntile++) {
                uint32_t bh0 = FB(WSH[ob0 + ntile * 8]);
                uint32_t bh1 = FB(WSH[ob1 + ntile * 8]);
                uint32_t bl0 = FB(WSL[ob0 + ntile * 8]);
                uint32_t bl1 = FB(WSL[ob1 + ntile * 8]);
                mma_tf32(acc[ntile], ah0, ah1, ah2, ah3, bh0, bh1);
                mma_tf32(acc[ntile], ah0, ah1, ah2, ah3, bl0, bl1);
                mma_tf32(acc[ntile], al0, al1, al2, al3, bh0, bh1);
            }
        }
        if (it < 23) RT_STORE(p ^ 1);
        __syncthreads();
        p ^= 1;
    }

    // epilogue: xenc = acc + enc_b  -> smem (overlays XSH region; all MMAs done)
    float* xe = (float*)(smem + RT_XSH);
#pragma unroll
    for (int ntile = 0; ntile < 8; ntile++) {
        const int cb = ntile * 8 + 2 * lc;
        const float ba = benc[cb], bb = benc[cb + 1];
        float* e0 = xe + (size_t)(m0 + lr) * XE_STR + cb;
        float* e1 = xe + (size_t)(m0 + lr + 8) * XE_STR + cb;
        e0[0] = acc[ntile][0] + ba;  e0[1] = acc[ntile][1] + bb;
        e1[0] = acc[ntile][2] + ba;  e1[1] = acc[ntile][3] + bb;
    }
    __syncthreads();

    // switch logits: 2 threads per token (256 thr = 128 tok), shfl reduce
    {
        int t = tid >> 1, hf = tid & 1;
        float l[E];
#pragma unroll
        for (int e = 0; e < E; e++) l[e] = hf ? 0.f : swbs[e];
        int r0 = hf * 32;
        const float* xrow_p = xe + (size_t)t * XE_STR;
        for (int r = r0; r < r0 + 32; r++) {
            float xv = xrow_p[r];
#pragma unroll
            for (int e = 0; e < E; e++) l[e] += xv * sws[r * E + e];
        }
#pragma unroll
        for (int e = 0; e < E; e++) l[e] += __shfl_xor_sync(0xffffffffu, l[e], 1);
        if (hf == 0) {
            float m = l[0]; int am = 0;
#pragma unroll
            for (int e = 1; e < E; e++) { if (l[e] > m) { m = l[e]; am = e; } }
            float s = 0.f;
#pragma unroll
            for (int e = 0; e < E; e++) s += expf(l[e] - m);
            int gt = base_t + t;
            g_pmax[gt] = 1.0f / s;
            int slot = atomicAdd(&g_counts[am], 1);
            g_toks[am * T_TOT + slot] = gt;
        }
    }
}

// ---------------- expert kernel: mma.sync tf32 (unchanged, proven) ----------
#define OFF_HS    0
#define OFF_POOL  34816
#define OFF_WS    (34816 + 36864)
#define OFF_TOK   104448
#define OFF_PM    104960
#define OFF_B1S   105472
#define OFF_B2S   105728
#define SMEM_TOTAL (105728 + 1024)

#define XS_STR  36
#define WS_STR  72
#define HS_STR  68
#define W2_STR  136

__global__ void __launch_bounds__(256)
expert_mma_kernel(const float* __restrict__ x,  const float* __restrict__ w1,
                  const float* __restrict__ b1, const float* __restrict__ w2,
                  const float* __restrict__ b2, float* __restrict__ outp)
{
    extern __shared__ char smem[];
    const int e   = blockIdx.y;
    const int cnt = g_counts[e];
    const int t0  = blockIdx.x * T_TILE;
    if (t0 >= cnt) return;
    const int nt = min(T_TILE, cnt - t0);

    const int tid  = threadIdx.x;
    const int wid  = tid >> 5;
    const int lane = tid & 31;
    const int lr   = lane >> 2;
    const int lc   = lane & 3;
    const int m0   = wid * 16;

    float* HS  = (float*)(smem + OFF_HS);
    float* XS  = (float*)(smem + OFF_POOL);
    float* WS  = (float*)(smem + OFF_WS);
    float* W2S = (float*)(smem + OFF_POOL);
    int*   toks = (int*)(smem + OFF_TOK);
    float* pm_s = (float*)(smem + OFF_PM);
    float* b1s  = (float*)(smem + OFF_B1S);
    float* b2s  = (float*)(smem + OFF_B2S);

    if (tid < 128) {
        int idx = t0 + ((tid < nt) ? tid : 0);
        int tok = g_toks[e * T_TOT + idx];
        toks[tid] = tok;
        pm_s[tid] = g_pmax[tok];
    }
    if (tid < 64) b1s[tid] = b1[e * R + tid];
    __syncthreads();

    const float* w1e = w1 + (size_t)e * H * R;
    int xrow[4], xk[4];
    const float* xgp[4];
#pragma unroll
    for (int j = 0; j < 4; j++) {
        int i = tid + j * 256;
        xrow[j] = i >> 3;  xk[j] = (i & 7) << 2;
        xgp[j] = x + (size_t)toks[xrow[j]] * H + xk[j];
    }
    int wkr[2], wn4[2];
#pragma unroll
    for (int j = 0; j < 2; j++) {
        int i = tid + j * 256;
        wkr[j] = i >> 4;  wn4[j] = (i & 15) << 2;
    }

    float4 xr[4], wr[2];
#define P1_LOAD(k0) { \
    _Pragma("unroll") for (int j = 0; j < 4; j++) xr[j] = *(const float4*)(xgp[j] + (k0)); \
    _Pragma("unroll") for (int j = 0; j < 2; j++) wr[j] = *(const float4*)(w1e + (size_t)((k0) + wkr[j]) * R + wn4[j]); }
#define P1_STORE(bf) { \
    _Pragma("unroll") for (int j = 0; j < 4; j++) { \
        float* d = XS + ((size_t)((bf) * 128 + xrow[j]) * XS_STR + xk[j]); \
        d[0] = tf32f(xr[j].x); d[1] = tf32f(xr[j].y); d[2] = tf32f(xr[j].z); d[3] = tf32f(xr[j].w); } \
    _Pragma("unroll") for (int j = 0; j < 2; j++) { \
        float* d = WS + ((size_t)((bf) * 32 + wkr[j]) * WS_STR + wn4[j]); \
        d[0] = tf32f(wr[j].x); d[1] = tf32f(wr[j].y); d[2] = tf32f(wr[j].z); d[3] = tf32f(wr[j].w); } }

    float acc[8][4];
#pragma unroll
    for (int i = 0; i < 8; i++)
#pragma unroll
        for (int j = 0; j < 4; j++) acc[i][j] = 0.f;

    P1_LOAD(0); P1_STORE(0); __syncthreads();
    int p = 0;
    for (int it = 0; it < 24; it++) {
        if (it < 23) P1_LOAD((it + 1) * 32);
#pragma unroll
        for (int ks = 0; ks < 4; ks++) {
            const int kk = ks * 8;
            const float* xb = XS + (size_t)(p * 128 + m0) * XS_STR + kk;
            uint32_t a0 = FB(xb[(size_t)lr * XS_STR + lc]);
            uint32_t a1 = FB(xb[(size_t)(lr + 8) * XS_STR + lc]);
            uint32_t a2 = FB(xb[(size_t)lr * XS_STR + lc + 4]);
            uint32_t a3 = FB(xb[(size_t)(lr + 8) * XS_STR + lc + 4]);
            const float* wb0 = WS + (size_t)(p * 32 + kk + lc) * WS_STR + lr;
            const float* wb1 = WS + (size_t)(p * 32 + kk + lc + 4) * WS_STR + lr;
#pragma unroll
            for (int ntile = 0; ntile < 8; ntile++) {
                uint32_t b0 = FB(wb0[ntile * 8]);
                uint32_t b1v = FB(wb1[ntile * 8]);
                mma_tf32(acc[ntile], a0, a1, a2, a3, b0, b1v);
            }
        }
        if (it < 23) P1_STORE(p ^ 1);
        __syncthreads();
        p ^= 1;
    }

#pragma unroll
    for (int ntile = 0; ntile < 8; ntile++) {
        const int cb = ntile * 8 + 2 * lc;
        const float bva = b1s[cb], bvb = b1s[cb + 1];
        float* h0 = HS + (size_t)(m0 + lr) * HS_STR + cb;
        float* h1 = HS + (size_t)(m0 + lr + 8) * HS_STR + cb;
        h0[0] = tf32f(gelu(acc[ntile][0] + bva));
        h0[1] = tf32f(gelu(acc[ntile][1] + bvb));
        h1[0] = tf32f(gelu(acc[ntile][2] + bva));
        h1[1] = tf32f(gelu(acc[ntile][3] + bvb));
    }
    __syncthreads();

    const float* w2e = w2 + (size_t)e * R * H;
    int w2k[8], w2n[8];
#pragma unroll
    for (int j = 0; j < 8; j++) {
        int i = tid + j * 256;
        w2k[j] = i >> 5;  w2n[j] = (i & 31) << 2;
    }
    float4 w2r[8];
#define P2_LOAD(n0) { \
    _Pragma("unroll") for (int j = 0; j < 8; j++) \
        w2r[j] = *(const float4*)(w2e + (size_t)w2k[j] * H + (n0) + w2n[j]); }
#define P2_STORE(bf) { \
    _Pragma("unroll") for (int j = 0; j < 8; j++) { \
        float* d = W2S + ((size_t)((bf) * 64 + w2k[j]) * W2_STR + w2n[j]); \
        d[0] = tf32f(w2r[j].x); d[1] = tf32f(w2r[j].y); d[2] = tf32f(w2r[j].z); d[3] = tf32f(w2r[j].w); } }

    P2_LOAD(0); P2_STORE(0);
    if (tid < 128) b2s[tid] = b2[(size_t)e * H + tid];
    __syncthreads();

    const bool ok0 = (m0 + lr) < nt;
    const bool ok1 = (m0 + lr + 8) < nt;
    const float pm0 = pm_s[m0 + lr];
    const float pm1 = pm_s[m0 + lr + 8];
    float* orow0 = outp + (size_t)toks[m0 + lr] * H;
    float* orow1 = outp + (size_t)toks[m0 + lr + 8] * H;

    uint32_t af[8][4];
#pragma unroll
    for (int ks = 0; ks < 8; ks++) {
        const int kk = ks * 8;
        const float* hb = HS + (size_t)m0 * HS_STR + kk;
        af[ks][0] = FB(hb[(size_t)lr * HS_STR + lc]);
        af[ks][1] = FB(hb[(size_t)(lr + 8) * HS_STR + lc]);
        af[ks][2] = FB(hb[(size_t)lr * HS_STR + lc + 4]);
        af[ks][3] = FB(hb[(size_t)(lr + 8) * HS_STR + lc + 4]);
    }

    int bf = 0;
    for (int nc = 0; nc < 6; nc++) {
        const int n0 = nc * 128;
        if (nc < 5) P2_LOAD(n0 + 128);

        float acc2[16][4];
#pragma unroll
        for (int i = 0; i < 16; i++)
#pragma unroll
            for (int j = 0; j < 4; j++) acc2[i][j] = 0.f;

#pragma unroll
        for (int ks = 0; ks < 8; ks++) {
            const int kk = ks * 8;
            const float* wb0 = W2S + (size_t)(bf * 64 + kk + lc) * W2_STR + lr;
            const float* wb1 = W2S + (size_t)(bf * 64 + kk + lc + 4) * W2_STR + lr;
#pragma unroll
            for (int ntile = 0; ntile < 16; ntile++) {
                uint32_t b0 = FB(wb0[ntile * 8]);
                uint32_t b1v = FB(wb1[ntile * 8]);
                mma_tf32(acc2[ntile], af[ks][0], af[ks][1], af[ks][2], af[ks][3], b0, b1v);
            }
        }

#pragma unroll
        for (int ntile = 0; ntile < 16; ntile++) {
            const int cb = ntile * 8 + 2 * lc;
            const float bva = b2s[bf * 128 + cb], bvb = b2s[bf * 128 + cb + 1];
            if (ok0) {
                float2 o = { (acc2[ntile][0] + bva) * pm0, (acc2[ntile][1] + bvb) * pm0 };
                *(float2*)(orow0 + n0 + cb) = o;
            }
            if (ok1) {
                float2 o = { (acc2[ntile][2] + bva) * pm1, (acc2[ntile][3] + bvb) * pm1 };
                *(float2*)(orow1 + n0 + cb) = o;
            }
        }

        if (nc < 5) {
            P2_STORE(bf ^ 1);
            if (tid < 128) b2s[(bf ^ 1) * 128 + tid] = b2[(size_t)e * H + n0 + 128 + tid];
        }
        __syncthreads();
        bf ^= 1;
    }
}

// ---------------- launch ----------------------------------------------------
extern "C" void kernel_launch(void* const* d_in, const int* in_sizes, int n_in,
                              void* d_out, int out_size) {
    const float* x     = (const float*)d_in[0];
    const float* enc_w = (const float*)d_in[1];
    const float* enc_b = (const float*)d_in[2];
    const float* sw_w  = (const float*)d_in[3];
    const float* sw_b  = (const float*)d_in[4];
    const float* w1    = (const float*)d_in[5];
    const float* b1    = (const float*)d_in[6];
    const float* w2    = (const float*)d_in[7];
    const float* b2    = (const float*)d_in[8];
    float* out = (float*)d_out;

    cudaFuncSetAttribute(router_mma_kernel,
                         cudaFuncAttributeMaxDynamicSharedMemorySize, SMEM_RT);
    cudaFuncSetAttribute(expert_mma_kernel,
                         cudaFuncAttributeMaxDynamicSharedMemorySize, SMEM_TOTAL);

    zero_counts_kernel<<<1, 32>>>();
    router_mma_kernel<<<T_TOT / T_TILE, 256, SMEM_RT>>>(x, enc_w, enc_b, sw_w, sw_b);
    expert_mma_kernel<<<dim3(T_TOT / T_TILE, E), 256, SMEM_TOTAL>>>(
        x, w1, b1, w2, b2, out);
}

// round 7
// speedup vs baseline: 4.4695x; 1.3612x over previous
#include <cuda_runtime.h>
#include <math.h>
#include <stdint.h>

#define H 768
#define R 64
#define E 8
#define T_TOT 16384
#define T_TILE 128

// ---------------- device global scratch -----------------------------------
__device__ int   g_counts[E];
__device__ int   g_toks[E * T_TOT];
__device__ float g_pmax[T_TOT];
__device__ float g_wc[H * E];    // combined router weight, c-interleaved layout
__device__ float g_bc[E];        // combined router bias

// ---------------- helpers ---------------------------------------------------
__device__ __forceinline__ float tf32f(float v) {
    uint32_t r; asm("cvt.rna.tf32.f32 %0, %1;" : "=r"(r) : "f"(v));
    return __uint_as_float(r);
}
__device__ __forceinline__ float gelu(float v) {
    return 0.5f * v * (1.0f + erff(v * 0.70710678118654752f));
}
__device__ __forceinline__ void mma_tf32(float c[4], uint32_t a0, uint32_t a1,
                                         uint32_t a2, uint32_t a3,
                                         uint32_t b0, uint32_t b1) {
    asm volatile(
        "mma.sync.aligned.m16n8k8.row.col.f32.tf32.tf32.f32 "
        "{%0,%1,%2,%3}, {%4,%5,%6,%7}, {%8,%9}, {%0,%1,%2,%3};"
        : "+f"(c[0]), "+f"(c[1]), "+f"(c[2]), "+f"(c[3])
        : "r"(a0), "r"(a1), "r"(a2), "r"(a3), "r"(b0), "r"(b1));
}
#define FB(x) __float_as_uint(x)

// ---------------- router prep: W_comb = enc_w @ sw_w  -----------------------
// Stored c-interleaved: entry (h, e) at [ ((h&3)*192 + (h>>2))*8 + e ]
// so that a warp reading rows h = j*128 + lane*4 + c hits contiguous memory.
__global__ void router_prep_kernel(const float* __restrict__ enc_w,
                                   const float* __restrict__ enc_b,
                                   const float* __restrict__ sw_w,
                                   const float* __restrict__ sw_b)
{
    int idx = blockIdx.x * 256 + threadIdx.x;     // 24 blocks * 256 = 6144 = H*E
    if (idx < H * E) {
        int h = idx >> 3, e = idx & 7;
        float s = 0.f;
#pragma unroll
        for (int r = 0; r < R; r++) s = fmaf(enc_w[h * R + r], sw_w[r * E + e], s);
        g_wc[((h & 3) * 192 + (h >> 2)) * 8 + e] = s;
    }
    if (blockIdx.x == 0 && threadIdx.x < E) {
        int e = threadIdx.x;
        float s = sw_b[e];
#pragma unroll
        for (int r = 0; r < R; r++) s = fmaf(enc_b[r], sw_w[r * E + e], s);
        g_bc[e] = s;
        g_counts[e] = 0;
    }
}

// ---------------- router: logits = x @ W_comb + b_comb ----------------------
// Warp handles 4 tokens. 31-shuffle butterfly reduces 32 (tok,e) partials so
// lane L ends with the full logit for (tok = L>>3, e = L&7).
__global__ __launch_bounds__(256) void router_lite_kernel(const float* __restrict__ x)
{
    const int tid  = threadIdx.x;
    const int wid  = tid >> 5;
    const int lane = tid & 31;
    const int tb   = (blockIdx.x * 8 + wid) * 4;   // token base (4 tokens)

    float acc[4][8];
#pragma unroll
    for (int t = 0; t < 4; t++)
#pragma unroll
        for (int e = 0; e < 8; e++) acc[t][e] = 0.f;

    const float* xp0 = x + (size_t)tb * H + lane * 4;

#pragma unroll
    for (int j = 0; j < 6; j++) {
        float4 xv[4];
#pragma unroll
        for (int t = 0; t < 4; t++)
            xv[t] = *(const float4*)(xp0 + (size_t)t * H + j * 128);
#pragma unroll
        for (int c = 0; c < 4; c++) {
            const float* wrow = g_wc + ((size_t)(c * 192 + j * 32 + lane) * 8);
            float4 w0 = *(const float4*)wrow;
            float4 w1 = *(const float4*)(wrow + 4);
#pragma unroll
            for (int t = 0; t < 4; t++) {
                float xs = (c == 0) ? xv[t].x : (c == 1) ? xv[t].y
                          : (c == 2) ? xv[t].z : xv[t].w;
                acc[t][0] += xs * w0.x; acc[t][1] += xs * w0.y;
                acc[t][2] += xs * w0.z; acc[t][3] += xs * w0.w;
                acc[t][4] += xs * w1.x; acc[t][5] += xs * w1.y;
                acc[t][6] += xs * w1.z; acc[t][7] += xs * w1.w;
            }
        }
    }

    // butterfly exchange-reduce: 32 partials -> lane L owns total for value L
    float a[32];
#pragma unroll
    for (int t = 0; t < 4; t++)
#pragma unroll
        for (int e = 0; e < 8; e++) a[t * 8 + e] = acc[t][e];

#pragma unroll
    for (int r = 0; r < 5; r++) {
        const int hn = 16 >> r;
        const bool up = (lane >> r) & 1;
#pragma unroll
        for (int j2 = 0; j2 < hn; j2++) {
            float pay  = up ? a[2 * j2] : a[2 * j2 + 1];
            float rec  = __shfl_xor_sync(0xffffffffu, pay, 1 << r);
            float keep = up ? a[2 * j2 + 1] : a[2 * j2];
            a[j2] = keep + rec;
        }
    }

    // 8-lane group softmax/argmax (lane L: token lane>>3, expert lane&7)
    const int e    = lane & 7;
    const int tloc = lane >> 3;
    float l = a[0] + g_bc[e];

    float m = l; int am = e;
#pragma unroll
    for (int off = 4; off >= 1; off >>= 1) {
        float om = __shfl_xor_sync(0xffffffffu, m, off);
        int   oa = __shfl_xor_sync(0xffffffffu, am, off);
        if (om > m || (om == m && oa < am)) { m = om; am = oa; }
    }
    float s = expf(l - m);
#pragma unroll
    for (int off = 4; off >= 1; off >>= 1) s += __shfl_xor_sync(0xffffffffu, s, off);

    if (e == 0) {
        int t = tb + tloc;
        g_pmax[t] = 1.0f / s;
        int slot = atomicAdd(&g_counts[am], 1);
        g_toks[am * T_TOT + slot] = t;
    }
}

// ---------------- expert kernel: mma.sync tf32 (unchanged, proven) ----------
#define OFF_HS    0
#define OFF_POOL  34816
#define OFF_WS    (34816 + 36864)
#define OFF_TOK   104448
#define OFF_PM    104960
#define OFF_B1S   105472
#define OFF_B2S   105728
#define SMEM_TOTAL (105728 + 1024)

#define XS_STR  36
#define WS_STR  72
#define HS_STR  68
#define W2_STR  136

__global__ void __launch_bounds__(256)
expert_mma_kernel(const float* __restrict__ x,  const float* __restrict__ w1,
                  const float* __restrict__ b1, const float* __restrict__ w2,
                  const float* __restrict__ b2, float* __restrict__ outp)
{
    extern __shared__ char smem[];
    const int e   = blockIdx.y;
    const int cnt = g_counts[e];
    const int t0  = blockIdx.x * T_TILE;
    if (t0 >= cnt) return;
    const int nt = min(T_TILE, cnt - t0);

    const int tid  = threadIdx.x;
    const int wid  = tid >> 5;
    const int lane = tid & 31;
    const int lr   = lane >> 2;
    const int lc   = lane & 3;
    const int m0   = wid * 16;

    float* HS  = (float*)(smem + OFF_HS);
    float* XS  = (float*)(smem + OFF_POOL);
    float* WS  = (float*)(smem + OFF_WS);
    float* W2S = (float*)(smem + OFF_POOL);
    int*   toks = (int*)(smem + OFF_TOK);
    float* pm_s = (float*)(smem + OFF_PM);
    float* b1s  = (float*)(smem + OFF_B1S);
    float* b2s  = (float*)(smem + OFF_B2S);

    if (tid < 128) {
        int idx = t0 + ((tid < nt) ? tid : 0);
        int tok = g_toks[e * T_TOT + idx];
        toks[tid] = tok;
        pm_s[tid] = g_pmax[tok];
    }
    if (tid < 64) b1s[tid] = b1[e * R + tid];
    __syncthreads();

    const float* w1e = w1 + (size_t)e * H * R;
    int xrow[4], xk[4];
    const float* xgp[4];
#pragma unroll
    for (int j = 0; j < 4; j++) {
        int i = tid + j * 256;
        xrow[j] = i >> 3;  xk[j] = (i & 7) << 2;
        xgp[j] = x + (size_t)toks[xrow[j]] * H + xk[j];
    }
    int wkr[2], wn4[2];
#pragma unroll
    for (int j = 0; j < 2; j++) {
        int i = tid + j * 256;
        wkr[j] = i >> 4;  wn4[j] = (i & 15) << 2;
    }

    float4 xr[4], wr[2];
#define P1_LOAD(k0) { \
    _Pragma("unroll") for (int j = 0; j < 4; j++) xr[j] = *(const float4*)(xgp[j] + (k0)); \
    _Pragma("unroll") for (int j = 0; j < 2; j++) wr[j] = *(const float4*)(w1e + (size_t)((k0) + wkr[j]) * R + wn4[j]); }
#define P1_STORE(bf) { \
    _Pragma("unroll") for (int j = 0; j < 4; j++) { \
        float* d = XS + ((size_t)((bf) * 128 + xrow[j]) * XS_STR + xk[j]); \
        d[0] = tf32f(xr[j].x); d[1] = tf32f(xr[j].y); d[2] = tf32f(xr[j].z); d[3] = tf32f(xr[j].w); } \
    _Pragma("unroll") for (int j = 0; j < 2; j++) { \
        float* d = WS + ((size_t)((bf) * 32 + wkr[j]) * WS_STR + wn4[j]); \
        d[0] = tf32f(wr[j].x); d[1] = tf32f(wr[j].y); d[2] = tf32f(wr[j].z); d[3] = tf32f(wr[j].w); } }

    float acc[8][4];
#pragma unroll
    for (int i = 0; i < 8; i++)
#pragma unroll
        for (int j = 0; j < 4; j++) acc[i][j] = 0.f;

    P1_LOAD(0); P1_STORE(0); __syncthreads();
    int p = 0;
    for (int it = 0; it < 24; it++) {
        if (it < 23) P1_LOAD((it + 1) * 32);
#pragma unroll
        for (int ks = 0; ks < 4; ks++) {
            const int kk = ks * 8;
            const float* xb = XS + (size_t)(p * 128 + m0) * XS_STR + kk;
            uint32_t a0 = FB(xb[(size_t)lr * XS_STR + lc]);
            uint32_t a1 = FB(xb[(size_t)(lr + 8) * XS_STR + lc]);
            uint32_t a2 = FB(xb[(size_t)lr * XS_STR + lc + 4]);
            uint32_t a3 = FB(xb[(size_t)(lr + 8) * XS_STR + lc + 4]);
            const float* wb0 = WS + (size_t)(p * 32 + kk + lc) * WS_STR + lr;
            const float* wb1 = WS + (size_t)(p * 32 + kk + lc + 4) * WS_STR + lr;
#pragma unroll
            for (int ntile = 0; ntile < 8; ntile++) {
                uint32_t b0 = FB(wb0[ntile * 8]);
                uint32_t b1v = FB(wb1[ntile * 8]);
                mma_tf32(acc[ntile], a0, a1, a2, a3, b0, b1v);
            }
        }
        if (it < 23) P1_STORE(p ^ 1);
        __syncthreads();
        p ^= 1;
    }

#pragma unroll
    for (int ntile = 0; ntile < 8; ntile++) {
        const int cb = ntile * 8 + 2 * lc;
        const float bva = b1s[cb], bvb = b1s[cb + 1];
        float* h0 = HS + (size_t)(m0 + lr) * HS_STR + cb;
        float* h1 = HS + (size_t)(m0 + lr + 8) * HS_STR + cb;
        h0[0] = tf32f(gelu(acc[ntile][0] + bva));
        h0[1] = tf32f(gelu(acc[ntile][1] + bvb));
        h1[0] = tf32f(gelu(acc[ntile][2] + bva));
        h1[1] = tf32f(gelu(acc[ntile][3] + bvb));
    }
    __syncthreads();

    const float* w2e = w2 + (size_t)e * R * H;
    int w2k[8], w2n[8];
#pragma unroll
    for (int j = 0; j < 8; j++) {
        int i = tid + j * 256;
        w2k[j] = i >> 5;  w2n[j] = (i & 31) << 2;
    }
    float4 w2r[8];
#define P2_LOAD(n0) { \
    _Pragma("unroll") for (int j = 0; j < 8; j++) \
        w2r[j] = *(const float4*)(w2e + (size_t)w2k[j] * H + (n0) + w2n[j]); }
#define P2_STORE(bf) { \
    _Pragma("unroll") for (int j = 0; j < 8; j++) { \
        float* d = W2S + ((size_t)((bf) * 64 + w2k[j]) * W2_STR + w2n[j]); \
        d[0] = tf32f(w2r[j].x); d[1] = tf32f(w2r[j].y); d[2] = tf32f(w2r[j].z); d[3] = tf32f(w2r[j].w); } }

    P2_LOAD(0); P2_STORE(0);
    if (tid < 128) b2s[tid] = b2[(size_t)e * H + tid];
    __syncthreads();

    const bool ok0 = (m0 + lr) < nt;
    const bool ok1 = (m0 + lr + 8) < nt;
    const float pm0 = pm_s[m0 + lr];
    const float pm1 = pm_s[m0 + lr + 8];
    float* orow0 = outp + (size_t)toks[m0 + lr] * H;
    float* orow1 = outp + (size_t)toks[m0 + lr + 8] * H;

    uint32_t af[8][4];
#pragma unroll
    for (int ks = 0; ks < 8; ks++) {
        const int kk = ks * 8;
        const float* hb = HS + (size_t)m0 * HS_STR + kk;
        af[ks][0] = FB(hb[(size_t)lr * HS_STR + lc]);
        af[ks][1] = FB(hb[(size_t)(lr + 8) * HS_STR + lc]);
        af[ks][2] = FB(hb[(size_t)lr * HS_STR + lc + 4]);
        af[ks][3] = FB(hb[(size_t)(lr + 8) * HS_STR + lc + 4]);
    }

    int bf = 0;
    for (int nc = 0; nc < 6; nc++) {
        const int n0 = nc * 128;
        if (nc < 5) P2_LOAD(n0 + 128);

        float acc2[16][4];
#pragma unroll
        for (int i = 0; i < 16; i++)
#pragma unroll
            for (int j = 0; j < 4; j++) acc2[i][j] = 0.f;

#pragma unroll
        for (int ks = 0; ks < 8; ks++) {
            const int kk = ks * 8;
            const float* wb0 = W2S + (size_t)(bf * 64 + kk + lc) * W2_STR + lr;
            const float* wb1 = W2S + (size_t)(bf * 64 + kk + lc + 4) * W2_STR + lr;
#pragma unroll
            for (int ntile = 0; ntile < 16; ntile++) {
                uint32_t b0 = FB(wb0[ntile * 8]);
                uint32_t b1v = FB(wb1[ntile * 8]);
                mma_tf32(acc2[ntile], af[ks][0], af[ks][1], af[ks][2], af[ks][3], b0, b1v);
            }
        }

#pragma unroll
        for (int ntile = 0; ntile < 16; ntile++) {
            const int cb = ntile * 8 + 2 * lc;
            const float bva = b2s[bf * 128 + cb], bvb = b2s[bf * 128 + cb + 1];
            if (ok0) {
                float2 o = { (acc2[ntile][0] + bva) * pm0, (acc2[ntile][1] + bvb) * pm0 };
                *(float2*)(orow0 + n0 + cb) = o;
            }
            if (ok1) {
                float2 o = { (acc2[ntile][2] + bva) * pm1, (acc2[ntile][3] + bvb) * pm1 };
                *(float2*)(orow1 + n0 + cb) = o;
            }
        }

        if (nc < 5) {
            P2_STORE(bf ^ 1);
            if (tid < 128) b2s[(bf ^ 1) * 128 + tid] = b2[(size_t)e * H + n0 + 128 + tid];
        }
        __syncthreads();
        bf ^= 1;
    }
}

// ---------------- launch ----------------------------------------------------
extern "C" void kernel_launch(void* const* d_in, const int* in_sizes, int n_in,
                              void* d_out, int out_size) {
    const float* x     = (const float*)d_in[0];
    const float* enc_w = (const float*)d_in[1];
    const float* enc_b = (const float*)d_in[2];
    const float* sw_w  = (const float*)d_in[3];
    const float* sw_b  = (const float*)d_in[4];
    const float* w1    = (const float*)d_in[5];
    const float* b1    = (const float*)d_in[6];
    const float* w2    = (const float*)d_in[7];
    const float* b2    = (const float*)d_in[8];
    float* out = (float*)d_out;

    cudaFuncSetAttribute(expert_mma_kernel,
                         cudaFuncAttributeMaxDynamicSharedMemorySize, SMEM_TOTAL);

    router_prep_kernel<<<24, 256>>>(enc_w, enc_b, sw_w, sw_b);
    router_lite_kernel<<<T_TOT / 32, 256>>>(x);
    expert_mma_kernel<<<dim3(T_TOT / T_TILE, E), 256, SMEM_TOTAL>>>(
        x, w1, b1, w2, b2, out);
}